// round 16
// baseline (speedup 1.0000x reference)
#include <cuda_runtime.h>
#include <cuda_fp16.h>

#define NN 50000
#define EE 800000
#define IND 128
#define EDD 16
#define HH 64
#define HH2 128
#define OUTD 8
#define NLAYER 4
#define NB 196              // ceil(NN/256)
#define NGROUP (NN / 8)     // 6250 node-groups of 8

typedef unsigned long long ull;
typedef long long ll;

// ---------------- scratch (static __device__, no allocations) ----------------
__device__ __align__(256) __half2 d_ea2[EE * 32];  // 102.4 MB: edge features fp16, DST-SORTED
__device__ __align__(256) int2  d_sp[EE];          // per sorted edge: {src node, original edge id}
__device__ __align__(256) int   d_rowStart[NN + 1];
__device__ __align__(256) int   d_cursor[NN];
__device__ __align__(256) int   d_bsum[NB];
__device__ __align__(256) float d_h[NN * HH];
__device__ __align__(256) float d_z[NN * HH];
__device__ __align__(256) __half2 d_z2[NN * 32];
__device__ __align__(256) float d_hin[NN * HH];

__device__ __forceinline__ float warpSum(float v) {
#pragma unroll
    for (int o = 16; o; o >>= 1) v += __shfl_xor_sync(0xffffffffu, v, o);
    return v;
}

// packed f32x2 helpers
__device__ __forceinline__ ull pk2(float lo, float hi) {
    ull r; asm("mov.b64 %0, {%1, %2};" : "=l"(r) : "f"(lo), "f"(hi)); return r;
}
__device__ __forceinline__ void upk2(ull v, float& lo, float& hi) {
    asm("mov.b64 {%0, %1}, %2;" : "=f"(lo), "=f"(hi) : "l"(v));
}
__device__ __forceinline__ void fma2(ull& d, ull a, ull b) {
    asm("fma.rn.f32x2 %0, %1, %2, %0;" : "+l"(d) : "l"(a), "l"(b));
}
__device__ __forceinline__ float ex2(float x) {
    float r; asm("ex2.approx.f32 %0, %1;" : "=f"(r) : "f"(x)); return r;
}
__device__ __forceinline__ __half2 h2bits(unsigned u) {
    __half2 h; *reinterpret_cast<unsigned*>(&h) = u; return h;
}

// per-block dtype probe: int64 data has high words 0 -> first 8 ull all < NN
__device__ __forceinline__ int probe64(const void* eiv) {
    const ull* p = (const ull*)eiv;
    int ok = 1;
#pragma unroll
    for (int i = 0; i < 8; i++)
        if (p[i] >= (ull)NN) ok = 0;
    return ok;
}

// ---------------- CSR build ----------------
__global__ void histK(const void* eiv) {
    __shared__ int is64s;
    if (threadIdx.x == 0) is64s = probe64(eiv);
    __syncthreads();
    int e = blockIdx.x * blockDim.x + threadIdx.x;
    if (e < EE) {
        int d = is64s ? (int)((const ll*)eiv)[EE + e] : ((const int*)eiv)[EE + e];
        if ((unsigned)d < (unsigned)NN) atomicAdd(&d_cursor[d], 1);
    }
}

__global__ void blockSumK() {
    __shared__ int s[256];
    int t = threadIdx.x;
    int i = blockIdx.x * 256 + t;
    s[t] = (i < NN) ? d_cursor[i] : 0;
    __syncthreads();
    for (int off = 128; off; off >>= 1) {
        if (t < off) s[t] += s[t + off];
        __syncthreads();
    }
    if (t == 0) d_bsum[blockIdx.x] = s[0];
}

// each block: scan the 196 block sums locally (redundant, cheap) + scan its own 256 counts
__global__ void rowStartK() {
    __shared__ int bsc[256];
    __shared__ int s[256];
    int t = threadIdx.x;
    int bv = (t < NB) ? d_bsum[t] : 0;
    bsc[t] = bv;
    __syncthreads();
    for (int off = 1; off < 256; off <<= 1) {
        int u = (t >= off) ? bsc[t - off] : 0;
        __syncthreads();
        bsc[t] += u;
        __syncthreads();
    }
    int boff = (blockIdx.x == 0) ? 0 : bsc[blockIdx.x - 1];
    if (blockIdx.x == 0 && t == 0) d_rowStart[NN] = bsc[255];

    int i = blockIdx.x * 256 + t;
    int v = (i < NN) ? d_cursor[i] : 0;
    s[t] = v;
    __syncthreads();
    for (int off = 1; off < 256; off <<= 1) {
        int u = (t >= off) ? s[t - off] : 0;
        __syncthreads();
        s[t] += u;
        __syncthreads();
    }
    int excl = s[t] - v + boff;
    if (i < NN) { d_rowStart[i] = excl; d_cursor[i] = excl; }
}

__global__ void scatterK(const void* eiv) {
    __shared__ int is64s;
    if (threadIdx.x == 0) is64s = probe64(eiv);
    __syncthreads();
    int e = blockIdx.x * blockDim.x + threadIdx.x;
    if (e < EE) {
        int s, d;
        if (is64s) { s = (int)((const ll*)eiv)[e]; d = (int)((const ll*)eiv)[EE + e]; }
        else       { s = ((const int*)eiv)[e];     d = ((const int*)eiv)[EE + e]; }
        if ((unsigned)d < (unsigned)NN && (unsigned)s < (unsigned)NN) {
            int p = atomicAdd(&d_cursor[d], 1);
            d_sp[p] = make_int2(s, e);
        }
    }
}

// ---------------- edge encoder: DST-SORTED output, gathered attr reads --------------------
// Weights in registers (R15 design). Each thread gathers its sorted edge's 16 attrs
// (64B random READ - latency-hidden), stages in smem; warp computes 32 edges, writing
// fully SEQUENTIAL 128B rows at the sorted positions. aggK then streams d_ea2.
__global__ __launch_bounds__(256) void eaSortK(const float* __restrict__ eattr,
                                               const float* __restrict__ eW,
                                               const float* __restrict__ eb) {
    __shared__ __align__(16) float satt[256 * 16];   // 16KB attr staging
    int t = threadIdx.x;
    int lane = t & 31, wid = t >> 5;
    int base = blockIdx.x * 256;                      // grid = EE/256 exactly

    // gather this thread's sorted edge attrs (random 64B read)
    {
        int e = __ldg(&d_sp[base + t]).y;
        const float4* ap = (const float4*)(eattr + (size_t)e * EDD);
        float4 a0 = __ldg(ap), a1 = __ldg(ap + 1), a2 = __ldg(ap + 2), a3 = __ldg(ap + 3);
        *(float4*)&satt[t * 16 + 0]  = a0;
        *(float4*)&satt[t * 16 + 4]  = a1;
        *(float4*)&satt[t * 16 + 8]  = a2;
        *(float4*)&satt[t * 16 + 12] = a3;
    }

    // per-lane weight slice (2 columns x 16 rows) in registers
    int c2 = lane * 2;
    ull wreg[16];
#pragma unroll
    for (int k = 0; k < 16; k++) {
        float2 w = *(const float2*)&eW[k * HH + c2];
        wreg[k] = pk2(w.x, w.y);
    }
    ull breg = pk2(__ldg(&eb[c2]), __ldg(&eb[c2 + 1]));
    __syncthreads();

    unsigned* gout = (unsigned*)(d_ea2 + (size_t)(base + wid * 32) * 32) + lane;
    const float2* at = (const float2*)&satt[wid * 32 * 16];

#pragma unroll 4
    for (int e8 = 0; e8 < 32; e8++) {
        ull acc = breg;
#pragma unroll
        for (int kk = 0; kk < 8; kk++) {
            float2 a = at[e8 * 8 + kk];              // LDS.64 broadcast
            fma2(acc, pk2(a.x, a.x), wreg[2 * kk]);
            fma2(acc, pk2(a.y, a.y), wreg[2 * kk + 1]);
        }
        float lo, hi; upk2(acc, lo, hi);
        __half2 hv = __floats2half2_rn(lo, hi);
        gout[e8 * 32] = *reinterpret_cast<unsigned*>(&hv);   // coalesced 128B line per edge
    }
}

// ---------------- node encoder: d_z/d_z2 = x @ node_W + node_b (8-node batch, f32x2) ------
// Also zeroes d_cursor for the next graph replay (runs after scatterK).
#define NODE_SMEM ((8192 + 64 + 8 * 1280) * 4)

__global__ __launch_bounds__(256) void nodeEncK(const float* __restrict__ x,
                                                const float* __restrict__ W,
                                                const float* __restrict__ b) {
    extern __shared__ float sm[];
    float* Ws = sm;                   // 128*64
    float* bs = Ws + 8192;            // 64
    float* stage = bs + 64;           // 8 * 1280
    if (blockIdx.x < NB) {
        int ci = blockIdx.x * 256 + threadIdx.x;
        if (ci < NN) d_cursor[ci] = 0;
    }
    for (int i = threadIdx.x; i < 8192; i += 256) Ws[i] = W[i];
    if (threadIdx.x < 64) bs[threadIdx.x] = b[threadIdx.x];
    __syncthreads();
    int lane = threadIdx.x & 31, wid = threadIdx.x >> 5;
    float* sx = stage + wid * 1280;
    int c2 = lane * 2;
    for (int g = blockIdx.x * 8 + wid; g < NGROUP; g += gridDim.x * 8) {
        int vbase = g * 8;
        const float* xp = x + (size_t)vbase * IND;
        for (int i = lane; i < 1024; i += 32) {
            int n = i >> 7, k = i & 127;
            sx[k * 10 + n] = xp[i];
        }
        __syncwarp();
        ull a0[4], a1[4];
        {
            ull bb0 = pk2(bs[c2], bs[c2]);
            ull bb1 = pk2(bs[c2 + 1], bs[c2 + 1]);
#pragma unroll
            for (int p = 0; p < 4; p++) { a0[p] = bb0; a1[p] = bb1; }
        }
#pragma unroll 8
        for (int k = 0; k < 128; k++) {
            float2 w = *(const float2*)&Ws[k * 64 + c2];
            ull wd0 = pk2(w.x, w.x), wd1 = pk2(w.y, w.y);
#pragma unroll
            for (int p = 0; p < 4; p++) {
                ull xp2 = *(const ull*)&sx[k * 10 + 2 * p];
                fma2(a0[p], xp2, wd0);
                fma2(a1[p], xp2, wd1);
            }
        }
#pragma unroll
        for (int p = 0; p < 4; p++) {
            float x00, x10, x01, x11;
            upk2(a0[p], x00, x10);
            upk2(a1[p], x01, x11);
            int v0 = vbase + 2 * p, v1 = v0 + 1;
            *(float2*)&d_z[(size_t)v0 * HH + c2] = make_float2(x00, x01);
            *(float2*)&d_z[(size_t)v1 * HH + c2] = make_float2(x10, x11);
            d_z2[(size_t)v0 * 32 + lane] = __floats2half2_rn(x00, x01);
            d_z2[(size_t)v1 * 32 + lane] = __floats2half2_rn(x10, x11);
        }
        __syncwarp();
    }
}

// ---------------- per-edge message math (half-warp per edge, 4 dims/lane) ----------------
__device__ __forceinline__ void msgMath(uint2 ea, uint2 zz, float tl2e,
                                        float s[4], float w[4]) {
    __half2 zero2 = __float2half2_rn(0.f);
    __half2 m20 = __hmax2(__hadd2(h2bits(zz.x), h2bits(ea.x)), zero2);
    __half2 m21 = __hmax2(__hadd2(h2bits(zz.y), h2bits(ea.y)), zero2);
    float2 ma = __half22float2(m20);
    float2 mb = __half22float2(m21);
    float p0 = ex2(ma.x * tl2e), p1 = ex2(ma.y * tl2e);
    float p2 = ex2(mb.x * tl2e), p3 = ex2(mb.y * tl2e);
    s[0] += p0; s[1] += p1; s[2] += p2; s[3] += p3;
    w[0] = fmaf(ma.x, p0, w[0]);
    w[1] = fmaf(ma.y, p1, w[1]);
    w[2] = fmaf(mb.x, p2, w[2]);
    w[3] = fmaf(mb.y, p3, w[3]);
}

// sorted edge position e+k: ea streamed sequentially (__ldcs), z2 gathered (__ldg, L2-hot)
__device__ __forceinline__ void edgePairS(int e, int k, int sub, float tl2e,
                                          float s[4], float w[4]) {
    int u = __ldg(&d_sp[e + k]).x;
    uint2 ea = __ldcs((const uint2*)d_ea2 + (size_t)(e + k) * 16 + sub);
    uint2 zz = __ldg((const uint2*)(d_z2 + (size_t)u * 32) + sub);
    msgMath(ea, zz, tl2e, s, w);
}

// ---------------- aggregation: d_hin = softmax-agg(msg) + z ----------------
// warp per node; half-warp per edge; ea2 sequential stream, z2 gather only.
// eps outside loop (constant shift cancels exactly in softmax).
__global__ __launch_bounds__(256) void aggK(const float* __restrict__ tptr, int layer) {
    int lane = threadIdx.x & 31, wid = threadIdx.x >> 5;
    int k = lane >> 4;          // half-warp id
    int sub = lane & 15;        // dim group
    float t = __ldg(&tptr[layer]);
    float tl2e = t * 1.4426950408889634f;
    int nwarp = gridDim.x << 3;
    for (int v = blockIdx.x * 8 + wid; v < NN; v += nwarp) {
        int rs = __ldg(&d_rowStart[v]), re = __ldg(&d_rowStart[v + 1]);
        float s[4] = {0.f, 0.f, 0.f, 0.f};
        float w[4] = {0.f, 0.f, 0.f, 0.f};
        int e = rs;
        for (; e + 4 <= re; e += 4) {
            edgePairS(e,     k, sub, tl2e, s, w);
            edgePairS(e + 2, k, sub, tl2e, s, w);
        }
        if (e + 2 <= re) { edgePairS(e, k, sub, tl2e, s, w); e += 2; }
        if (e < re && k == 0) edgePairS(e, 0, sub, tl2e, s, w);   // odd tail: half-warp 0 only
#pragma unroll
        for (int j = 0; j < 4; j++) {
            s[j] += __shfl_xor_sync(0xffffffffu, s[j], 16);
            w[j] += __shfl_xor_sync(0xffffffffu, w[j], 16);
        }
        if (k == 0) {
            float4 zv = *(const float4*)&d_z[(size_t)v * HH + sub * 4];
            float4 o;
            o.x = w[0] / (s[0] + 1e-16f) + 1e-7f + zv.x;
            o.y = w[1] / (s[1] + 1e-16f) + 1e-7f + zv.y;
            o.z = w[2] / (s[2] + 1e-16f) + 1e-7f + zv.z;
            o.w = w[3] / (s[3] + 1e-16f) + 1e-7f + zv.w;
            *(float4*)&d_hin[(size_t)v * HH + sub * 4] = o;
        }
    }
}

// ---------------- MLP: h = [res +] MLP2(relu(LN(MLP1(hin)))) ; optional z_next -------------
#define MLP_SMEM ((8192 + 8192 + 384 + 64 + 64 + 64 + 8 * 1280) * 4)

__global__ void mlpK(const float* __restrict__ W1, const float* __restrict__ b1,
                     const float* __restrict__ g1, const float* __restrict__ be1,
                     const float* __restrict__ W2, const float* __restrict__ b2,
                     const float* __restrict__ gn, const float* __restrict__ bn,
                     int residual, int writeZ) {
    extern __shared__ float sm[];
    float* W1s  = sm;                 // 8192
    float* W2s  = W1s + 8192;         // 8192
    float* b1s  = W2s + 8192;         // 128
    float* g1s  = b1s + 128;          // 128
    float* be1s = g1s + 128;          // 128
    float* b2s  = be1s + 128;         // 64
    float* gns  = b2s + 64;           // 64
    float* bns  = gns + 64;           // 64
    float* sball = bns + 64;          // 8 * 1280

    for (int i = threadIdx.x; i < 8192; i += blockDim.x) { W1s[i] = W1[i]; W2s[i] = W2[i]; }
    for (int i = threadIdx.x; i < 128; i += blockDim.x) { b1s[i] = b1[i]; g1s[i] = g1[i]; be1s[i] = be1[i]; }
    if (threadIdx.x < 64) {
        b2s[threadIdx.x] = b2[threadIdx.x];
        if (writeZ) { gns[threadIdx.x] = gn[threadIdx.x]; bns[threadIdx.x] = bn[threadIdx.x]; }
    }
    __syncthreads();

    int lane = threadIdx.x & 31, wid = threadIdx.x >> 5;
    float* sb = sball + wid * 1280;
    int o = lane * 4;      // MLP1 output cols [o, o+4)
    int c2 = lane * 2;     // MLP2 output cols [c2, c2+2)

    for (int g = blockIdx.x * 8 + wid; g < NGROUP; g += gridDim.x * 8) {
        int vbase = g * 8;

        // stage h: sb[k*10 + n] = hin[vbase+n][k]
        const float* hp = d_hin + (size_t)vbase * HH;
        for (int i = lane; i < 512; i += 32) {
            int n = i >> 6, k = i & 63;
            sb[k * 10 + n] = hp[i];
        }
        __syncwarp();

        // ---- MLP1: 64 -> 128, 4 node-pairs x 4 outputs, packed f32x2 ----
        ull acc[4][4];
#pragma unroll
        for (int j = 0; j < 4; j++) {
            ull bj = pk2(b1s[o + j], b1s[o + j]);
#pragma unroll
            for (int p = 0; p < 4; p++) acc[p][j] = bj;
        }
#pragma unroll 8
        for (int k = 0; k < 64; k++) {
            float4 w = *(const float4*)&W1s[k * 128 + o];
            ull wd0 = pk2(w.x, w.x), wd1 = pk2(w.y, w.y);
            ull wd2 = pk2(w.z, w.z), wd3 = pk2(w.w, w.w);
#pragma unroll
            for (int p = 0; p < 4; p++) {
                ull hpair = *(const ull*)&sb[k * 10 + 2 * p];
                fma2(acc[p][0], hpair, wd0);
                fma2(acc[p][1], hpair, wd1);
                fma2(acc[p][2], hpair, wd2);
                fma2(acc[p][3], hpair, wd3);
            }
        }
        __syncwarp();

        // ---- LayerNorm(128) + relu, write z into sb ----
#pragma unroll
        for (int p = 0; p < 4; p++) {
            float a0[4], a1[4];
#pragma unroll
            for (int j = 0; j < 4; j++) upk2(acc[p][j], a0[j], a1[j]);
            float mu0 = warpSum(a0[0] + a0[1] + a0[2] + a0[3]) * (1.f / HH2);
            float mu1 = warpSum(a1[0] + a1[1] + a1[2] + a1[3]) * (1.f / HH2);
            float dv0 = 0.f, dv1 = 0.f;
#pragma unroll
            for (int j = 0; j < 4; j++) {
                a0[j] -= mu0; a1[j] -= mu1;
                dv0 = fmaf(a0[j], a0[j], dv0);
                dv1 = fmaf(a1[j], a1[j], dv1);
            }
            float inv0 = rsqrtf(warpSum(dv0) * (1.f / HH2) + 1e-5f);
            float inv1 = rsqrtf(warpSum(dv1) * (1.f / HH2) + 1e-5f);
#pragma unroll
            for (int j = 0; j < 4; j++) {
                float z0 = fmaxf(fmaf(a0[j] * inv0, g1s[o + j], be1s[o + j]), 0.f);
                float z1 = fmaxf(fmaf(a1[j] * inv1, g1s[o + j], be1s[o + j]), 0.f);
                *(ull*)&sb[(o + j) * 10 + 2 * p] = pk2(z0, z1);
            }
        }
        __syncwarp();

        // ---- MLP2: 128 -> 64, 4 node-pairs x 2 outputs ----
        ull oa[4][2];
        {
            ull bb0 = pk2(b2s[c2], b2s[c2]);
            ull bb1 = pk2(b2s[c2 + 1], b2s[c2 + 1]);
#pragma unroll
            for (int p = 0; p < 4; p++) { oa[p][0] = bb0; oa[p][1] = bb1; }
        }
#pragma unroll 8
        for (int k = 0; k < 128; k++) {
            float2 w = *(const float2*)&W2s[k * 64 + c2];
            ull wd0 = pk2(w.x, w.x), wd1 = pk2(w.y, w.y);
#pragma unroll
            for (int p = 0; p < 4; p++) {
                ull zp = *(const ull*)&sb[k * 10 + 2 * p];
                fma2(oa[p][0], zp, wd0);
                fma2(oa[p][1], zp, wd1);
            }
        }

        // ---- epilogue: residual, store d_h, optional z_next = relu(LN(h)) ----
#pragma unroll
        for (int p = 0; p < 4; p++) {
            float o00, o10, o01, o11;
            upk2(oa[p][0], o00, o10);   // output col c2   : nodes 2p, 2p+1
            upk2(oa[p][1], o01, o11);   // output col c2+1
#pragma unroll
            for (int e = 0; e < 2; e++) {
                int v = vbase + 2 * p + e;
                float h0 = e ? o10 : o00;
                float h1 = e ? o11 : o01;
                if (residual) {
                    float2 hv = *(const float2*)&d_h[(size_t)v * HH + c2];
                    h0 += hv.x; h1 += hv.y;
                }
                *(float2*)&d_h[(size_t)v * HH + c2] = make_float2(h0, h1);
                if (writeZ) {
                    float mu = warpSum(h0 + h1) * (1.f / HH);
                    float d0 = h0 - mu, d1 = h1 - mu;
                    float var = warpSum(d0 * d0 + d1 * d1) * (1.f / HH);
                    float inv = rsqrtf(var + 1e-5f);
                    float z0 = fmaxf(fmaf(d0 * inv, gns[c2], bns[c2]), 0.f);
                    float z1 = fmaxf(fmaf(d1 * inv, gns[c2 + 1], bns[c2 + 1]), 0.f);
                    *(float2*)&d_z[(size_t)v * HH + c2] = make_float2(z0, z1);
                    d_z2[(size_t)v * 32 + lane] = __floats2half2_rn(z0, z1);
                }
            }
        }
        __syncwarp();
    }
}

// ---------------- final: out = relu(LN(d_h, g0, b0)) @ lin_W + lin_b ----------------
__global__ void finalK(const float* __restrict__ g, const float* __restrict__ b,
                       const float* __restrict__ lW, const float* __restrict__ lb,
                       float* __restrict__ out) {
    __shared__ float Ws[HH * OUTD];
    __shared__ float zs[8][HH];
    for (int i = threadIdx.x; i < HH * OUTD; i += blockDim.x) Ws[i] = lW[i];
    __syncthreads();
    int lane = threadIdx.x & 31, wi = threadIdx.x >> 5;
    int warp = (blockIdx.x << 3) + wi;
    int nwarp = gridDim.x << 3;
    int c = 2 * lane;
    for (int v = warp; v < NN; v += nwarp) {
        float2 hv = *(const float2*)&d_h[(size_t)v * HH + c];
        float mu = warpSum(hv.x + hv.y) * (1.f / HH);
        float d0 = hv.x - mu, d1 = hv.y - mu;
        float var = warpSum(d0 * d0 + d1 * d1) * (1.f / HH);
        float inv = rsqrtf(var + 1e-5f);
        zs[wi][c]     = fmaxf(fmaf(d0 * inv, __ldg(&g[c]),     __ldg(&b[c])),     0.f);
        zs[wi][c + 1] = fmaxf(fmaf(d1 * inv, __ldg(&g[c + 1]), __ldg(&b[c + 1])), 0.f);
        __syncwarp();
        if (lane < OUTD) {
            float acc = __ldg(&lb[lane]);
#pragma unroll
            for (int k = 0; k < HH; k++) acc = fmaf(zs[wi][k], Ws[k * OUTD + lane], acc);
            out[(size_t)v * OUTD + lane] = acc;
        }
        __syncwarp();
    }
}

// ---------------- launch ----------------
extern "C" void kernel_launch(void* const* d_in, const int* in_sizes, int n_in,
                              void* d_out, int out_size) {
    const float* x     = (const float*)d_in[0];
    const float* eattr = (const float*)d_in[1];
    const float* nodeW = (const float*)d_in[2];
    const float* nodeb = (const float*)d_in[3];
    const float* edgeW = (const float*)d_in[4];
    const float* edgeb = (const float*)d_in[5];
    const float* convT = (const float*)d_in[6];
    const float* cW1   = (const float*)d_in[7];
    const float* cb1   = (const float*)d_in[8];
    const float* cg1   = (const float*)d_in[9];
    const float* cbe1  = (const float*)d_in[10];
    const float* cW2   = (const float*)d_in[11];
    const float* cb2   = (const float*)d_in[12];
    const float* lng   = (const float*)d_in[13];
    const float* lnb   = (const float*)d_in[14];
    const float* linW  = (const float*)d_in[15];
    const float* linb  = (const float*)d_in[16];
    const void*  ei    = d_in[17];   // int32 or int64, probed on device per block

    cudaFuncSetAttribute(mlpK, cudaFuncAttributeMaxDynamicSharedMemorySize, MLP_SMEM);
    cudaFuncSetAttribute(nodeEncK, cudaFuncAttributeMaxDynamicSharedMemorySize, NODE_SMEM);

    // CSR build (cursor zeroed by nodeEncK each replay; globals start zero-initialized)
    histK<<<(EE + 255) / 256, 256>>>(ei);
    blockSumK<<<NB, 256>>>();
    rowStartK<<<NB, 256>>>();
    scatterK<<<(EE + 255) / 256, 256>>>(ei);            // launch #4 (profiled)

    // encoders: eaSortK needs d_sp (after scatter); writes sorted, coalesced ea2 rows
    eaSortK<<<EE / 256, 256>>>(eattr, edgeW, edgeb);
    nodeEncK<<<296, 256, NODE_SMEM>>>(x, nodeW, nodeb); // also zeroes d_cursor

    // split layers: agg (sequential ea2 stream + z2 gather), then smem-resident MLP
    for (int l = 0; l < NLAYER; l++) {
        aggK<<<1184, 256>>>(convT, l);
        int writeZ = (l < NLAYER - 1);
        const float* gn = writeZ ? (lng + (l + 1) * HH) : lng;
        const float* bn = writeZ ? (lnb + (l + 1) * HH) : lnb;
        mlpK<<<296, 256, MLP_SMEM>>>(cW1 + l * HH * HH2, cb1 + l * HH2,
                                     cg1 + l * HH2, cbe1 + l * HH2,
                                     cW2 + l * HH2 * HH, cb2 + l * HH,
                                     gn, bn, (l > 0) ? 1 : 0, writeZ);
    }

    // final projection (LN with layer-0 params)
    finalK<<<592, 256>>>(lng, lnb, linW, linb, (float*)d_out);
}

// round 17
// speedup vs baseline: 1.0284x; 1.0284x over previous
#include <cuda_runtime.h>
#include <cuda_fp16.h>

#define NN 50000
#define EE 800000
#define IND 128
#define EDD 16
#define HH 64
#define HH2 128
#define OUTD 8
#define NLAYER 4
#define NB 196              // ceil(NN/256)
#define NG16 (NN / 16)      // 3125 node-groups of 16

typedef unsigned long long ull;
typedef long long ll;

// ---------------- scratch (static __device__, no allocations) ----------------
__device__ __align__(256) __half2 d_ea2[EE * 32];  // 102.4 MB: edge features fp16, DST-SORTED
__device__ __align__(256) int2  d_sp[EE];          // per sorted edge: {src node, original edge id}
__device__ __align__(256) int   d_rowStart[NN + 1];
__device__ __align__(256) int   d_cursor[NN];
__device__ __align__(256) int   d_bsum[NB];
__device__ __align__(256) float d_h[NN * HH];
__device__ __align__(256) float d_z[NN * HH];
__device__ __align__(256) __half2 d_z2[NN * 32];
__device__ __align__(256) float d_hin[NN * HH];

__device__ __forceinline__ float warpSum(float v) {
#pragma unroll
    for (int o = 16; o; o >>= 1) v += __shfl_xor_sync(0xffffffffu, v, o);
    return v;
}

// packed f32x2 helpers
__device__ __forceinline__ ull pk2(float lo, float hi) {
    ull r; asm("mov.b64 %0, {%1, %2};" : "=l"(r) : "f"(lo), "f"(hi)); return r;
}
__device__ __forceinline__ void upk2(ull v, float& lo, float& hi) {
    asm("mov.b64 {%0, %1}, %2;" : "=f"(lo), "=f"(hi) : "l"(v));
}
__device__ __forceinline__ void fma2(ull& d, ull a, ull b) {
    asm("fma.rn.f32x2 %0, %1, %2, %0;" : "+l"(d) : "l"(a), "l"(b));
}
__device__ __forceinline__ float ex2(float x) {
    float r; asm("ex2.approx.f32 %0, %1;" : "=f"(r) : "f"(x)); return r;
}
__device__ __forceinline__ __half2 h2bits(unsigned u) {
    __half2 h; *reinterpret_cast<unsigned*>(&h) = u; return h;
}

// per-block dtype probe: int64 data has high words 0 -> first 8 ull all < NN
__device__ __forceinline__ int probe64(const void* eiv) {
    const ull* p = (const ull*)eiv;
    int ok = 1;
#pragma unroll
    for (int i = 0; i < 8; i++)
        if (p[i] >= (ull)NN) ok = 0;
    return ok;
}

// ---------------- CSR build ----------------
__global__ void histK(const void* eiv) {
    __shared__ int is64s;
    if (threadIdx.x == 0) is64s = probe64(eiv);
    __syncthreads();
    int e = blockIdx.x * blockDim.x + threadIdx.x;
    if (e < EE) {
        int d = is64s ? (int)((const ll*)eiv)[EE + e] : ((const int*)eiv)[EE + e];
        if ((unsigned)d < (unsigned)NN) atomicAdd(&d_cursor[d], 1);
    }
}

__global__ void blockSumK() {
    __shared__ int s[256];
    int t = threadIdx.x;
    int i = blockIdx.x * 256 + t;
    s[t] = (i < NN) ? d_cursor[i] : 0;
    __syncthreads();
    for (int off = 128; off; off >>= 1) {
        if (t < off) s[t] += s[t + off];
        __syncthreads();
    }
    if (t == 0) d_bsum[blockIdx.x] = s[0];
}

// each block: scan the 196 block sums locally (redundant, cheap) + scan its own 256 counts
__global__ void rowStartK() {
    __shared__ int bsc[256];
    __shared__ int s[256];
    int t = threadIdx.x;
    int bv = (t < NB) ? d_bsum[t] : 0;
    bsc[t] = bv;
    __syncthreads();
    for (int off = 1; off < 256; off <<= 1) {
        int u = (t >= off) ? bsc[t - off] : 0;
        __syncthreads();
        bsc[t] += u;
        __syncthreads();
    }
    int boff = (blockIdx.x == 0) ? 0 : bsc[blockIdx.x - 1];
    if (blockIdx.x == 0 && t == 0) d_rowStart[NN] = bsc[255];

    int i = blockIdx.x * 256 + t;
    int v = (i < NN) ? d_cursor[i] : 0;
    s[t] = v;
    __syncthreads();
    for (int off = 1; off < 256; off <<= 1) {
        int u = (t >= off) ? s[t - off] : 0;
        __syncthreads();
        s[t] += u;
        __syncthreads();
    }
    int excl = s[t] - v + boff;
    if (i < NN) { d_rowStart[i] = excl; d_cursor[i] = excl; }
}

__global__ void scatterK(const void* eiv) {
    __shared__ int is64s;
    if (threadIdx.x == 0) is64s = probe64(eiv);
    __syncthreads();
    int e = blockIdx.x * blockDim.x + threadIdx.x;
    if (e < EE) {
        int s, d;
        if (is64s) { s = (int)((const ll*)eiv)[e]; d = (int)((const ll*)eiv)[EE + e]; }
        else       { s = ((const int*)eiv)[e];     d = ((const int*)eiv)[EE + e]; }
        if ((unsigned)d < (unsigned)NN && (unsigned)s < (unsigned)NN) {
            int p = atomicAdd(&d_cursor[d], 1);
            d_sp[p] = make_int2(s, e);
        }
    }
}

// ---------------- edge encoder: DST-SORTED output, gathered attr reads --------------------
// Weights in registers. Each thread gathers its sorted edge's 16 attrs (64B random read,
// latency-hidden), stages in smem; warp computes 32 edges, writing fully SEQUENTIAL
// 128B rows at the sorted positions. aggK then streams d_ea2.
__global__ __launch_bounds__(256) void eaSortK(const float* __restrict__ eattr,
                                               const float* __restrict__ eW,
                                               const float* __restrict__ eb) {
    __shared__ __align__(16) float satt[256 * 16];   // 16KB attr staging
    int t = threadIdx.x;
    int lane = t & 31, wid = t >> 5;
    int base = blockIdx.x * 256;                      // grid = EE/256 exactly

    // gather this thread's sorted edge attrs (random 64B read)
    {
        int e = __ldg(&d_sp[base + t]).y;
        const float4* ap = (const float4*)(eattr + (size_t)e * EDD);
        float4 a0 = __ldg(ap), a1 = __ldg(ap + 1), a2 = __ldg(ap + 2), a3 = __ldg(ap + 3);
        *(float4*)&satt[t * 16 + 0]  = a0;
        *(float4*)&satt[t * 16 + 4]  = a1;
        *(float4*)&satt[t * 16 + 8]  = a2;
        *(float4*)&satt[t * 16 + 12] = a3;
    }

    // per-lane weight slice (2 columns x 16 rows) in registers
    int c2 = lane * 2;
    ull wreg[16];
#pragma unroll
    for (int k = 0; k < 16; k++) {
        float2 w = *(const float2*)&eW[k * HH + c2];
        wreg[k] = pk2(w.x, w.y);
    }
    ull breg = pk2(__ldg(&eb[c2]), __ldg(&eb[c2 + 1]));
    __syncthreads();

    unsigned* gout = (unsigned*)(d_ea2 + (size_t)(base + wid * 32) * 32) + lane;
    const float2* at = (const float2*)&satt[wid * 32 * 16];

#pragma unroll 4
    for (int e8 = 0; e8 < 32; e8++) {
        ull acc = breg;
#pragma unroll
        for (int kk = 0; kk < 8; kk++) {
            float2 a = at[e8 * 8 + kk];              // LDS.64 broadcast
            fma2(acc, pk2(a.x, a.x), wreg[2 * kk]);
            fma2(acc, pk2(a.y, a.y), wreg[2 * kk + 1]);
        }
        float lo, hi; upk2(acc, lo, hi);
        __half2 hv = __floats2half2_rn(lo, hi);
        gout[e8 * 32] = *reinterpret_cast<unsigned*>(&hv);   // coalesced 128B line per edge
    }
}

// ---------------- node encoder: d_z/d_z2 = x @ node_W + node_b (8-node batch, f32x2) ------
// Also zeroes d_cursor for the next graph replay (runs after scatterK).
#define NODE_SMEM ((8192 + 64 + 8 * 1280) * 4)
#define NGROUP8 (NN / 8)

__global__ __launch_bounds__(256) void nodeEncK(const float* __restrict__ x,
                                                const float* __restrict__ W,
                                                const float* __restrict__ b) {
    extern __shared__ float sm[];
    float* Ws = sm;                   // 128*64
    float* bs = Ws + 8192;            // 64
    float* stage = bs + 64;           // 8 * 1280
    if (blockIdx.x < NB) {
        int ci = blockIdx.x * 256 + threadIdx.x;
        if (ci < NN) d_cursor[ci] = 0;
    }
    for (int i = threadIdx.x; i < 8192; i += 256) Ws[i] = W[i];
    if (threadIdx.x < 64) bs[threadIdx.x] = b[threadIdx.x];
    __syncthreads();
    int lane = threadIdx.x & 31, wid = threadIdx.x >> 5;
    float* sx = stage + wid * 1280;
    int c2 = lane * 2;
    for (int g = blockIdx.x * 8 + wid; g < NGROUP8; g += gridDim.x * 8) {
        int vbase = g * 8;
        const float* xp = x + (size_t)vbase * IND;
        for (int i = lane; i < 1024; i += 32) {
            int n = i >> 7, k = i & 127;
            sx[k * 10 + n] = xp[i];
        }
        __syncwarp();
        ull a0[4], a1[4];
        {
            ull bb0 = pk2(bs[c2], bs[c2]);
            ull bb1 = pk2(bs[c2 + 1], bs[c2 + 1]);
#pragma unroll
            for (int p = 0; p < 4; p++) { a0[p] = bb0; a1[p] = bb1; }
        }
#pragma unroll 8
        for (int k = 0; k < 128; k++) {
            float2 w = *(const float2*)&Ws[k * 64 + c2];
            ull wd0 = pk2(w.x, w.x), wd1 = pk2(w.y, w.y);
#pragma unroll
            for (int p = 0; p < 4; p++) {
                ull xp2 = *(const ull*)&sx[k * 10 + 2 * p];
                fma2(a0[p], xp2, wd0);
                fma2(a1[p], xp2, wd1);
            }
        }
#pragma unroll
        for (int p = 0; p < 4; p++) {
            float x00, x10, x01, x11;
            upk2(a0[p], x00, x10);
            upk2(a1[p], x01, x11);
            int v0 = vbase + 2 * p, v1 = v0 + 1;
            *(float2*)&d_z[(size_t)v0 * HH + c2] = make_float2(x00, x01);
            *(float2*)&d_z[(size_t)v1 * HH + c2] = make_float2(x10, x11);
            d_z2[(size_t)v0 * 32 + lane] = __floats2half2_rn(x00, x01);
            d_z2[(size_t)v1 * 32 + lane] = __floats2half2_rn(x10, x11);
        }
        __syncwarp();
    }
}

// ---------------- per-edge message math (half-warp per edge, 4 dims/lane) ----------------
__device__ __forceinline__ void msgMath(uint2 ea, uint2 zz, float tl2e,
                                        float s[4], float w[4]) {
    __half2 zero2 = __float2half2_rn(0.f);
    __half2 m20 = __hmax2(__hadd2(h2bits(zz.x), h2bits(ea.x)), zero2);
    __half2 m21 = __hmax2(__hadd2(h2bits(zz.y), h2bits(ea.y)), zero2);
    float2 ma = __half22float2(m20);
    float2 mb = __half22float2(m21);
    float p0 = ex2(ma.x * tl2e), p1 = ex2(ma.y * tl2e);
    float p2 = ex2(mb.x * tl2e), p3 = ex2(mb.y * tl2e);
    s[0] += p0; s[1] += p1; s[2] += p2; s[3] += p3;
    w[0] = fmaf(ma.x, p0, w[0]);
    w[1] = fmaf(ma.y, p1, w[1]);
    w[2] = fmaf(mb.x, p2, w[2]);
    w[3] = fmaf(mb.y, p3, w[3]);
}

// sorted edge position e+k: ea streamed sequentially (__ldcs), z2 gathered (__ldg, L2-hot)
__device__ __forceinline__ void edgePairS(int e, int k, int sub, float tl2e,
                                          float s[4], float w[4]) {
    int u = __ldg(&d_sp[e + k]).x;
    uint2 ea = __ldcs((const uint2*)d_ea2 + (size_t)(e + k) * 16 + sub);
    uint2 zz = __ldg((const uint2*)(d_z2 + (size_t)u * 32) + sub);
    msgMath(ea, zz, tl2e, s, w);
}

// ---------------- aggregation: d_hin = softmax-agg(msg) + z ----------------
// warp per node; half-warp per edge; ea2 sequential stream, z2 gather only.
// eps outside loop (constant shift cancels exactly in softmax).
__global__ __launch_bounds__(256) void aggK(const float* __restrict__ tptr, int layer) {
    int lane = threadIdx.x & 31, wid = threadIdx.x >> 5;
    int k = lane >> 4;          // half-warp id
    int sub = lane & 15;        // dim group
    float t = __ldg(&tptr[layer]);
    float tl2e = t * 1.4426950408889634f;
    int nwarp = gridDim.x << 3;
    for (int v = blockIdx.x * 8 + wid; v < NN; v += nwarp) {
        int rs = __ldg(&d_rowStart[v]), re = __ldg(&d_rowStart[v + 1]);
        float s[4] = {0.f, 0.f, 0.f, 0.f};
        float w[4] = {0.f, 0.f, 0.f, 0.f};
        int e = rs;
        for (; e + 4 <= re; e += 4) {
            edgePairS(e,     k, sub, tl2e, s, w);
            edgePairS(e + 2, k, sub, tl2e, s, w);
        }
        if (e + 2 <= re) { edgePairS(e, k, sub, tl2e, s, w); e += 2; }
        if (e < re && k == 0) edgePairS(e, 0, sub, tl2e, s, w);   // odd tail: half-warp 0 only
#pragma unroll
        for (int j = 0; j < 4; j++) {
            s[j] += __shfl_xor_sync(0xffffffffu, s[j], 16);
            w[j] += __shfl_xor_sync(0xffffffffu, w[j], 16);
        }
        if (k == 0) {
            float4 zv = *(const float4*)&d_z[(size_t)v * HH + sub * 4];
            float4 o;
            o.x = __fdividef(w[0], s[0] + 1e-16f) + 1e-7f + zv.x;
            o.y = __fdividef(w[1], s[1] + 1e-16f) + 1e-7f + zv.y;
            o.z = __fdividef(w[2], s[2] + 1e-16f) + 1e-7f + zv.z;
            o.w = __fdividef(w[3], s[3] + 1e-16f) + 1e-7f + zv.w;
            *(float4*)&d_hin[(size_t)v * HH + sub * 4] = o;
        }
    }
}

// ---------------- MLP: 16-node batch per warp, 1 block/SM -------------------
// h = [res +] MLP2(relu(LN(MLP1(hin)))) ; optional z_next.
// Weights amortized over 16 nodes: smem crossbar per node halves vs 8-batch.
#define MLP_SMEM ((8192 + 8192 + 384 + 64 + 64 + 64 + 8 * (128 * 18)) * 4)

__global__ __launch_bounds__(256, 1)
void mlpK(const float* __restrict__ W1, const float* __restrict__ b1,
          const float* __restrict__ g1, const float* __restrict__ be1,
          const float* __restrict__ W2, const float* __restrict__ b2,
          const float* __restrict__ gn, const float* __restrict__ bn,
          int residual, int writeZ) {
    extern __shared__ float sm[];
    float* W1s  = sm;                 // 8192
    float* W2s  = W1s + 8192;         // 8192
    float* b1s  = W2s + 8192;         // 128
    float* g1s  = b1s + 128;          // 128
    float* be1s = g1s + 128;          // 128
    float* b2s  = be1s + 128;         // 64
    float* gns  = b2s + 64;           // 64
    float* bns  = gns + 64;           // 64
    float* sball = bns + 64;          // 8 * 2304

    for (int i = threadIdx.x; i < 8192; i += blockDim.x) { W1s[i] = W1[i]; W2s[i] = W2[i]; }
    for (int i = threadIdx.x; i < 128; i += blockDim.x) { b1s[i] = b1[i]; g1s[i] = g1[i]; be1s[i] = be1[i]; }
    if (threadIdx.x < 64) {
        b2s[threadIdx.x] = b2[threadIdx.x];
        if (writeZ) { gns[threadIdx.x] = gn[threadIdx.x]; bns[threadIdx.x] = bn[threadIdx.x]; }
    }
    __syncthreads();

    int lane = threadIdx.x & 31, wid = threadIdx.x >> 5;
    float* sb = sball + wid * 2304;   // 128 rows x 18 (16 nodes + pad 2)
    int o = lane * 4;      // MLP1 output cols [o, o+4)
    int c2 = lane * 2;     // MLP2 output cols [c2, c2+2)

    for (int g = blockIdx.x * 8 + wid; g < NG16; g += gridDim.x * 8) {
        int vbase = g * 16;

        // stage h: sb[k*18 + n] = hin[vbase+n][k], 16 nodes
        const float* hp = d_hin + (size_t)vbase * HH;
        for (int i = lane; i < 1024; i += 32) {
            int n = i >> 6, k = i & 63;
            sb[k * 18 + n] = hp[i];
        }
        __syncwarp();

        // ---- MLP1: 64 -> 128, 8 node-pairs x 4 outputs, packed f32x2 ----
        ull acc[8][4];
#pragma unroll
        for (int j = 0; j < 4; j++) {
            ull bj = pk2(b1s[o + j], b1s[o + j]);
#pragma unroll
            for (int p = 0; p < 8; p++) acc[p][j] = bj;
        }
#pragma unroll 4
        for (int k = 0; k < 64; k++) {
            float4 w = *(const float4*)&W1s[k * 128 + o];
            ull wd0 = pk2(w.x, w.x), wd1 = pk2(w.y, w.y);
            ull wd2 = pk2(w.z, w.z), wd3 = pk2(w.w, w.w);
#pragma unroll
            for (int p = 0; p < 8; p++) {
                ull hpair = *(const ull*)&sb[k * 18 + 2 * p];
                fma2(acc[p][0], hpair, wd0);
                fma2(acc[p][1], hpair, wd1);
                fma2(acc[p][2], hpair, wd2);
                fma2(acc[p][3], hpair, wd3);
            }
        }
        __syncwarp();

        // ---- LayerNorm(128) + relu, write z into sb ----
#pragma unroll
        for (int p = 0; p < 8; p++) {
            float a0[4], a1[4];
#pragma unroll
            for (int j = 0; j < 4; j++) upk2(acc[p][j], a0[j], a1[j]);
            float mu0 = warpSum(a0[0] + a0[1] + a0[2] + a0[3]) * (1.f / HH2);
            float mu1 = warpSum(a1[0] + a1[1] + a1[2] + a1[3]) * (1.f / HH2);
            float dv0 = 0.f, dv1 = 0.f;
#pragma unroll
            for (int j = 0; j < 4; j++) {
                a0[j] -= mu0; a1[j] -= mu1;
                dv0 = fmaf(a0[j], a0[j], dv0);
                dv1 = fmaf(a1[j], a1[j], dv1);
            }
            float inv0 = rsqrtf(warpSum(dv0) * (1.f / HH2) + 1e-5f);
            float inv1 = rsqrtf(warpSum(dv1) * (1.f / HH2) + 1e-5f);
#pragma unroll
            for (int j = 0; j < 4; j++) {
                float z0 = fmaxf(fmaf(a0[j] * inv0, g1s[o + j], be1s[o + j]), 0.f);
                float z1 = fmaxf(fmaf(a1[j] * inv1, g1s[o + j], be1s[o + j]), 0.f);
                *(ull*)&sb[(o + j) * 18 + 2 * p] = pk2(z0, z1);
            }
        }
        __syncwarp();

        // ---- MLP2: 128 -> 64, 8 node-pairs x 2 outputs ----
        ull oa[8][2];
        {
            ull bb0 = pk2(b2s[c2], b2s[c2]);
            ull bb1 = pk2(b2s[c2 + 1], b2s[c2 + 1]);
#pragma unroll
            for (int p = 0; p < 8; p++) { oa[p][0] = bb0; oa[p][1] = bb1; }
        }
#pragma unroll 4
        for (int k = 0; k < 128; k++) {
            float2 w = *(const float2*)&W2s[k * 64 + c2];
            ull wd0 = pk2(w.x, w.x), wd1 = pk2(w.y, w.y);
#pragma unroll
            for (int p = 0; p < 8; p++) {
                ull zp = *(const ull*)&sb[k * 18 + 2 * p];
                fma2(oa[p][0], zp, wd0);
                fma2(oa[p][1], zp, wd1);
            }
        }

        // ---- epilogue: residual, store d_h, optional z_next = relu(LN(h)) ----
#pragma unroll
        for (int p = 0; p < 8; p++) {
            float o00, o10, o01, o11;
            upk2(oa[p][0], o00, o10);   // output col c2   : nodes 2p, 2p+1
            upk2(oa[p][1], o01, o11);   // output col c2+1
#pragma unroll
            for (int e = 0; e < 2; e++) {
                int v = vbase + 2 * p + e;
                float h0 = e ? o10 : o00;
                float h1 = e ? o11 : o01;
                if (residual) {
                    float2 hv = *(const float2*)&d_h[(size_t)v * HH + c2];
                    h0 += hv.x; h1 += hv.y;
                }
                *(float2*)&d_h[(size_t)v * HH + c2] = make_float2(h0, h1);
                if (writeZ) {
                    float mu = warpSum(h0 + h1) * (1.f / HH);
                    float d0 = h0 - mu, d1 = h1 - mu;
                    float var = warpSum(d0 * d0 + d1 * d1) * (1.f / HH);
                    float inv = rsqrtf(var + 1e-5f);
                    float z0 = fmaxf(fmaf(d0 * inv, gns[c2], bns[c2]), 0.f);
                    float z1 = fmaxf(fmaf(d1 * inv, gns[c2 + 1], bns[c2 + 1]), 0.f);
                    *(float2*)&d_z[(size_t)v * HH + c2] = make_float2(z0, z1);
                    d_z2[(size_t)v * 32 + lane] = __floats2half2_rn(z0, z1);
                }
            }
        }
        __syncwarp();
    }
}

// ---------------- final: out = relu(LN(d_h, g0, b0)) @ lin_W + lin_b ----------------
__global__ void finalK(const float* __restrict__ g, const float* __restrict__ b,
                       const float* __restrict__ lW, const float* __restrict__ lb,
                       float* __restrict__ out) {
    __shared__ float Ws[HH * OUTD];
    __shared__ float zs[8][HH];
    for (int i = threadIdx.x; i < HH * OUTD; i += blockDim.x) Ws[i] = lW[i];
    __syncthreads();
    int lane = threadIdx.x & 31, wi = threadIdx.x >> 5;
    int warp = (blockIdx.x << 3) + wi;
    int nwarp = gridDim.x << 3;
    int c = 2 * lane;
    for (int v = warp; v < NN; v += nwarp) {
        float2 hv = *(const float2*)&d_h[(size_t)v * HH + c];
        float mu = warpSum(hv.x + hv.y) * (1.f / HH);
        float d0 = hv.x - mu, d1 = hv.y - mu;
        float var = warpSum(d0 * d0 + d1 * d1) * (1.f / HH);
        float inv = rsqrtf(var + 1e-5f);
        zs[wi][c]     = fmaxf(fmaf(d0 * inv, __ldg(&g[c]),     __ldg(&b[c])),     0.f);
        zs[wi][c + 1] = fmaxf(fmaf(d1 * inv, __ldg(&g[c + 1]), __ldg(&b[c + 1])), 0.f);
        __syncwarp();
        if (lane < OUTD) {
            float acc = __ldg(&lb[lane]);
#pragma unroll
            for (int k = 0; k < HH; k++) acc = fmaf(zs[wi][k], Ws[k * OUTD + lane], acc);
            out[(size_t)v * OUTD + lane] = acc;
        }
        __syncwarp();
    }
}

// ---------------- launch ----------------
extern "C" void kernel_launch(void* const* d_in, const int* in_sizes, int n_in,
                              void* d_out, int out_size) {
    const float* x     = (const float*)d_in[0];
    const float* eattr = (const float*)d_in[1];
    const float* nodeW = (const float*)d_in[2];
    const float* nodeb = (const float*)d_in[3];
    const float* edgeW = (const float*)d_in[4];
    const float* edgeb = (const float*)d_in[5];
    const float* convT = (const float*)d_in[6];
    const float* cW1   = (const float*)d_in[7];
    const float* cb1   = (const float*)d_in[8];
    const float* cg1   = (const float*)d_in[9];
    const float* cbe1  = (const float*)d_in[10];
    const float* cW2   = (const float*)d_in[11];
    const float* cb2   = (const float*)d_in[12];
    const float* lng   = (const float*)d_in[13];
    const float* lnb   = (const float*)d_in[14];
    const float* linW  = (const float*)d_in[15];
    const float* linb  = (const float*)d_in[16];
    const void*  ei    = d_in[17];   // int32 or int64, probed on device per block

    cudaFuncSetAttribute(mlpK, cudaFuncAttributeMaxDynamicSharedMemorySize, MLP_SMEM);
    cudaFuncSetAttribute(nodeEncK, cudaFuncAttributeMaxDynamicSharedMemorySize, NODE_SMEM);

    // CSR build (cursor zeroed by nodeEncK each replay; globals start zero-initialized)
    histK<<<(EE + 255) / 256, 256>>>(ei);
    blockSumK<<<NB, 256>>>();
    rowStartK<<<NB, 256>>>();
    scatterK<<<(EE + 255) / 256, 256>>>(ei);            // launch #4 (profiled)

    // encoders: eaSortK needs d_sp (after scatter); writes sorted, coalesced ea2 rows
    eaSortK<<<EE / 256, 256>>>(eattr, edgeW, edgeb);
    nodeEncK<<<296, 256, NODE_SMEM>>>(x, nodeW, nodeb); // also zeroes d_cursor

    // split layers: agg (sequential ea2 stream + z2 gather), then 16-batch MLP (1 blk/SM)
    for (int l = 0; l < NLAYER; l++) {
        aggK<<<1184, 256>>>(convT, l);
        int writeZ = (l < NLAYER - 1);
        const float* gn = writeZ ? (lng + (l + 1) * HH) : lng;
        const float* bn = writeZ ? (lnb + (l + 1) * HH) : lnb;
        mlpK<<<148, 256, MLP_SMEM>>>(cW1 + l * HH * HH2, cb1 + l * HH2,
                                     cg1 + l * HH2, cbe1 + l * HH2,
                                     cW2 + l * HH2 * HH, cb2 + l * HH,
                                     gn, bn, (l > 0) ? 1 : 0, writeZ);
    }

    // final projection (LN with layer-0 params)
    finalK<<<592, 256>>>(lng, lnb, linW, linb, (float*)d_out);
}